// round 1
// baseline (speedup 1.0000x reference)
#include <cuda_runtime.h>
#include <math.h>

#define N_PTS   32768
#define M_CENT  2048
#define K_NB    32
#define D_IN    64
#define D0      67
#define H1DIM   64
#define H2DIM   128
#define RAD2    0.25f

// ---------------- device scratch (no allocation allowed) ----------------
__device__ float d_sx[N_PTS];
__device__ float d_sy[N_PTS];
__device__ float d_sz[N_PTS];
__device__ int   d_gidx[M_CENT * K_NB];
__device__ unsigned long long d_keys[16];   // double-buffered 8-CTA argmax slots

// ---------------- kernel 0: AoS -> SoA transpose ----------------
__global__ void transpose_kernel(const float* __restrict__ xyz) {
    int i = blockIdx.x * blockDim.x + threadIdx.x;
    if (i < N_PTS) {
        d_sx[i] = xyz[3 * i + 0];
        d_sy[i] = xyz[3 * i + 1];
        d_sz[i] = xyz[3 * i + 2];
    }
}

// ---------------- kernel 1: farthest point sampling ----------------
// 8-CTA cluster; every thread owns 8 points fully in registers (xyz + running
// min-dist). Per iteration: update dists vs current centroid, per-thread max,
// warp/CTA reduce of a packed (dist_bits<<32 | (0xFFFFFFFF-idx)) key so that
// u64-max == argmax with first-index tie-break, exchange 8 CTA keys through
// global memory (release/acquire) around a cluster barrier, then every CTA
// reads the winner's coordinates from the SoA arrays.
#define FPS_CTAS 8
#define FPS_T    512
#define PPC      (N_PTS / FPS_CTAS)   // 4096
#define PPT      (PPC / FPS_T)        // 8

__global__ void __cluster_dims__(FPS_CTAS, 1, 1) __launch_bounds__(FPS_T, 1)
fps_kernel(float* __restrict__ new_xyz) {
    __shared__ unsigned long long s_w[FPS_T / 32];
    __shared__ float s_c[3];

    const int t  = threadIdx.x;
    const int cr = blockIdx.x;            // cluster rank == block idx (grid == cluster)
    const int base = cr * PPC + t;        // interleaved ownership, stride FPS_T

    float px[PPT], py[PPT], pz[PPT], pd[PPT];
#pragma unroll
    for (int k = 0; k < PPT; k++) {
        int p = base + k * FPS_T;
        px[k] = d_sx[p];
        py[k] = d_sy[p];
        pz[k] = d_sz[p];
        pd[k] = 1e38f;
    }

    if (t == 0) { s_c[0] = d_sx[0]; s_c[1] = d_sy[0]; s_c[2] = d_sz[0]; }
    __syncthreads();

    for (int i = 0; i < M_CENT; i++) {
        const float cx = s_c[0], cy = s_c[1], cz = s_c[2];
        if (cr == 0 && t == 0) {
            new_xyz[3 * i + 0] = cx;
            new_xyz[3 * i + 1] = cy;
            new_xyz[3 * i + 2] = cz;
        }

        // update dists + per-thread argmax (loop order gives lowest-index tie-break
        // within a thread because owned indices increase with k)
        float bd = -1.0f; int bi = 0;
#pragma unroll
        for (int k = 0; k < PPT; k++) {
            float dx = px[k] - cx;
            float dy = py[k] - cy;
            float dz = pz[k] - cz;
            // match XLA: (dx*dx + dy*dy) + dz*dz, no FMA contraction
            float d = __fadd_rn(__fadd_rn(__fmul_rn(dx, dx), __fmul_rn(dy, dy)),
                                __fmul_rn(dz, dz));
            float nd = fminf(pd[k], d);
            pd[k] = nd;
            if (nd > bd) { bd = nd; bi = base + k * FPS_T; }
        }

        // packed key: larger dist wins, equal dist -> smaller index wins
        unsigned long long key =
            ((unsigned long long)__float_as_uint(bd) << 32) |
            (unsigned long long)(0xFFFFFFFFu - (unsigned)bi);

#pragma unroll
        for (int o = 16; o > 0; o >>= 1) {
            unsigned long long v = __shfl_xor_sync(0xFFFFFFFFu, key, o);
            if (v > key) key = v;
        }
        if ((t & 31) == 0) s_w[t >> 5] = key;
        __syncthreads();

        if (t < 32) {
            unsigned long long v = (t < FPS_T / 32) ? s_w[t] : 0ull;
#pragma unroll
            for (int o = 8; o > 0; o >>= 1) {
                unsigned long long u = __shfl_xor_sync(0xFFFFFFFFu, v, o);
                if (u > v) v = u;
            }
            if (t == 0) {
                asm volatile("st.release.gpu.global.u64 [%0], %1;"
                             :: "l"(&d_keys[(i & 1) * FPS_CTAS + cr]), "l"(v)
                             : "memory");
            }
        }

        asm volatile("barrier.cluster.arrive.aligned;" ::: "memory");
        asm volatile("barrier.cluster.wait.aligned;" ::: "memory");

        if (t == 0) {
            unsigned long long w = 0ull;
#pragma unroll
            for (int r = 0; r < FPS_CTAS; r++) {
                unsigned long long v;
                asm volatile("ld.acquire.gpu.global.u64 %0, [%1];"
                             : "=l"(v)
                             : "l"(&d_keys[(i & 1) * FPS_CTAS + r])
                             : "memory");
                if (v > w) w = v;
            }
            unsigned fi = 0xFFFFFFFFu - (unsigned)(w & 0xFFFFFFFFull);
            s_c[0] = d_sx[fi]; s_c[1] = d_sy[fi]; s_c[2] = d_sz[fi];
        }
        __syncthreads();
    }
}

// ---------------- kernel 2: ball query (top-32 smallest within radius) ----------------
// One block per centroid. Compact in-radius (dist2,idx) keys to SMEM; then:
//  - count > 32: 32 rounds of parallel argmin (key = dist2_bits<<32 | idx, so
//    u64-min == lexicographic (dist2, idx) min) -> matches stable top_k set.
//  - count <= 32: take all, fill remainder with lowest-index out-of-radius
//    points (all masked values equal 1e9 -> stable top_k picks lowest indices).
// Order within the 32 is irrelevant (max-pool downstream is order-invariant).
#define BQ_T 256
#define CAP  4096

__global__ void __launch_bounds__(BQ_T)
bq_kernel(const float* __restrict__ new_xyz) {
    __shared__ unsigned long long list[CAP];
    __shared__ int s_cnt;
    __shared__ unsigned long long s_k[BQ_T / 32];
    __shared__ int s_p[BQ_T / 32];

    const int m = blockIdx.x, t = threadIdx.x;
    if (t == 0) s_cnt = 0;
    __syncthreads();

    const float cx = new_xyz[3 * m + 0];
    const float cy = new_xyz[3 * m + 1];
    const float cz = new_xyz[3 * m + 2];

    for (int p = t; p < N_PTS; p += BQ_T) {
        float dx = d_sx[p] - cx;
        float dy = d_sy[p] - cy;
        float dz = d_sz[p] - cz;
        float d2 = __fadd_rn(__fadd_rn(__fmul_rn(dx, dx), __fmul_rn(dy, dy)),
                             __fmul_rn(dz, dz));
        if (d2 <= RAD2) {
            int pos = atomicAdd(&s_cnt, 1);
            if (pos < CAP)
                list[pos] = ((unsigned long long)__float_as_uint(d2) << 32) |
                            (unsigned long long)(unsigned)p;
        }
    }
    __syncthreads();

    int n = s_cnt;
    if (n > CAP) n = CAP;

    if (n > K_NB) {
        for (int r = 0; r < K_NB; r++) {
            unsigned long long k = ~0ull; int pos = -1;
            for (int q = t; q < n; q += BQ_T) {
                unsigned long long v = list[q];
                if (v < k) { k = v; pos = q; }
            }
#pragma unroll
            for (int o = 16; o > 0; o >>= 1) {
                unsigned long long k2 = __shfl_xor_sync(0xFFFFFFFFu, k, o);
                int p2 = __shfl_xor_sync(0xFFFFFFFFu, pos, o);
                if (k2 < k) { k = k2; pos = p2; }
            }
            if ((t & 31) == 0) { s_k[t >> 5] = k; s_p[t >> 5] = pos; }
            __syncthreads();
            if (t == 0) {
                unsigned long long bk = ~0ull; int bp = -1;
#pragma unroll
                for (int w = 0; w < BQ_T / 32; w++)
                    if (s_k[w] < bk) { bk = s_k[w]; bp = s_p[w]; }
                d_gidx[m * K_NB + r] = (int)(bk & 0xFFFFFFFFull);
                list[bp] = ~0ull;   // remove winner
            }
            __syncthreads();
        }
    } else {
        if (t == 0) {
            int w = 0;
            for (int q = 0; q < n; q++)
                d_gidx[m * K_NB + w++] = (int)(list[q] & 0xFFFFFFFFull);
            for (int p = 0; w < K_NB; p++) {
                float dx = d_sx[p] - cx;
                float dy = d_sy[p] - cy;
                float dz = d_sz[p] - cz;
                float d2 = __fadd_rn(__fadd_rn(__fmul_rn(dx, dx), __fmul_rn(dy, dy)),
                                     __fmul_rn(dz, dz));
                if (d2 > RAD2) d_gidx[m * K_NB + w++] = p;
            }
        }
    }
}

// ---------------- kernel 3: grouped MLP (67->64 GELU, 64->128 GELU) + max-pool ----------------
__device__ __forceinline__ float gelu_exact(float x) {
    return 0.5f * x * (1.0f + erff(x * 0.70710678118654752f));
}

#define MLP_T 128

__global__ void __launch_bounds__(MLP_T)
mlp_kernel(const float* __restrict__ xyz,  const float* __restrict__ feat,
           const float* __restrict__ W1,   const float* __restrict__ b1,
           const float* __restrict__ W2,   const float* __restrict__ b2,
           const float* __restrict__ new_xyz, float* __restrict__ pooled) {
    __shared__ float s_g[K_NB * D0];     // grouped input  [32][67]
    __shared__ float s_h[K_NB * H1DIM];  // hidden         [32][64]
    __shared__ int   s_idx[K_NB];

    const int m = blockIdx.x, t = threadIdx.x;
    if (t < K_NB) s_idx[t] = d_gidx[m * K_NB + t];
    __syncthreads();

    const float nx = new_xyz[3 * m + 0];
    const float ny = new_xyz[3 * m + 1];
    const float nz = new_xyz[3 * m + 2];

    // gather [g_xyz | feat]
    for (int e = t; e < K_NB * D0; e += MLP_T) {
        int j = e / D0, k = e - j * D0;
        int id = s_idx[j];
        float v;
        if (k < 3) {
            float c = (k == 0) ? nx : (k == 1) ? ny : nz;
            v = xyz[id * 3 + k] - c;
        } else {
            v = feat[id * D_IN + (k - 3)];
        }
        s_g[j * D0 + k] = v;
    }
    __syncthreads();

    // layer 1: thread t handles row j = t&31, channels [grp*16, grp*16+16)
    {
        const int j = t & 31, grp = t >> 5;
        float acc[16];
#pragma unroll
        for (int cc = 0; cc < 16; cc++) acc[cc] = __ldg(&b1[grp * 16 + cc]);
        for (int k = 0; k < D0; k++) {
            float gk = s_g[j * D0 + k];
            const float* w = &W1[k * H1DIM + grp * 16];
#pragma unroll
            for (int cc = 0; cc < 16; cc++)
                acc[cc] = fmaf(gk, __ldg(&w[cc]), acc[cc]);
        }
#pragma unroll
        for (int cc = 0; cc < 16; cc++)
            s_h[j * H1DIM + grp * 16 + cc] = gelu_exact(acc[cc]);
    }
    __syncthreads();

    // layer 2 + max-pool: thread t == output channel; 4-row register tile over j
    {
        float pm = -3.4e38f;
        const float bb = __ldg(&b2[t]);
        for (int j0 = 0; j0 < K_NB; j0 += 4) {
            float a0 = bb, a1 = bb, a2 = bb, a3 = bb;
            const float* h0 = &s_h[(j0 + 0) * H1DIM];
            const float* h1 = &s_h[(j0 + 1) * H1DIM];
            const float* h2 = &s_h[(j0 + 2) * H1DIM];
            const float* h3 = &s_h[(j0 + 3) * H1DIM];
            for (int k = 0; k < H1DIM; k++) {
                float w = __ldg(&W2[k * H2DIM + t]);
                a0 = fmaf(h0[k], w, a0);
                a1 = fmaf(h1[k], w, a1);
                a2 = fmaf(h2[k], w, a2);
                a3 = fmaf(h3[k], w, a3);
            }
            pm = fmaxf(pm, gelu_exact(a0));
            pm = fmaxf(pm, gelu_exact(a1));
            pm = fmaxf(pm, gelu_exact(a2));
            pm = fmaxf(pm, gelu_exact(a3));
        }
        pooled[m * H2DIM + t] = pm;
    }
}

// ---------------- launch ----------------
extern "C" void kernel_launch(void* const* d_in, const int* in_sizes, int n_in,
                              void* d_out, int out_size) {
    const float* xyz  = (const float*)d_in[0];
    const float* feat = (const float*)d_in[1];
    const float* W1   = (const float*)d_in[2];
    const float* b1   = (const float*)d_in[3];
    const float* W2   = (const float*)d_in[4];
    const float* b2   = (const float*)d_in[5];

    float* out     = (float*)d_out;
    float* new_xyz = out;                 // [2048, 3]
    float* pooled  = out + M_CENT * 3;    // [2048, 128]

    transpose_kernel<<<(N_PTS + 255) / 256, 256>>>(xyz);
    fps_kernel<<<FPS_CTAS, FPS_T>>>(new_xyz);
    bq_kernel<<<M_CENT, BQ_T>>>(new_xyz);
    mlp_kernel<<<M_CENT, MLP_T>>>(xyz, feat, W1, b1, W2, b2, new_xyz, pooled);
}

// round 2
// speedup vs baseline: 2.3341x; 2.3341x over previous
#include <cuda_runtime.h>
#include <math.h>
#include <stdint.h>

#define N_PTS   32768
#define M_CENT  2048
#define K_NB    32
#define D_IN    64
#define D0      67
#define H1DIM   64
#define H2DIM   128
#define RAD2    0.25f

// ---------------- device scratch (no allocation allowed) ----------------
__device__ float d_sx[N_PTS];
__device__ float d_sy[N_PTS];
__device__ float d_sz[N_PTS];
__device__ int   d_gidx[M_CENT * K_NB];

__device__ __forceinline__ uint32_t smem_u32(const void* p) {
    uint32_t a;
    asm("{ .reg .u64 t; cvta.to.shared.u64 t, %1; cvt.u32.u64 %0, t; }"
        : "=r"(a) : "l"(p));
    return a;
}

// ---------------- kernel 0: AoS -> SoA transpose ----------------
__global__ void transpose_kernel(const float* __restrict__ xyz) {
    int i = blockIdx.x * blockDim.x + threadIdx.x;
    if (i < N_PTS) {
        d_sx[i] = xyz[3 * i + 0];
        d_sy[i] = xyz[3 * i + 1];
        d_sz[i] = xyz[3 * i + 2];
    }
}

// ---------------- kernel 1: farthest point sampling ----------------
// 8-CTA cluster, all point state in registers. Per iteration the CTA winner
// (key + coords) is pushed into every CTA's SMEM via DSMEM st.async with
// mbarrier complete_tx; each thread then picks the global winner locally.
// No cluster barrier, no global-memory round trips on the critical path.
#define FPS_CTAS 8
#define FPS_T    512
#define PPC      (N_PTS / FPS_CTAS)   // 4096
#define PPT      (PPC / FPS_T)        // 8
#define SLOT_BYTES 24                 // key(8) + cxy(8) + cz(8)
#define EXPECT_TX  (FPS_CTAS * SLOT_BYTES)  // 192

__device__ __forceinline__ void mbar_wait(uint32_t mbar, uint32_t parity) {
    asm volatile(
        "{\n\t"
        ".reg .pred P;\n\t"
        "WAIT_%=:\n\t"
        "mbarrier.try_wait.parity.acquire.cta.shared::cta.b64 P, [%0], %1, 0x989680;\n\t"
        "@P bra DONE_%=;\n\t"
        "bra WAIT_%=;\n\t"
        "DONE_%=:\n\t"
        "}"
        :: "r"(mbar), "r"(parity) : "memory");
}

__global__ void __cluster_dims__(FPS_CTAS, 1, 1) __launch_bounds__(FPS_T, 1)
fps_kernel(float* __restrict__ new_xyz) {
    __shared__ unsigned long long s_slot[2][FPS_CTAS][3];  // [buf][rank][key,cxy,cz]
    __shared__ unsigned long long s_mbar[2];
    __shared__ unsigned long long s_rkey[FPS_T / 32];
    __shared__ float s_rcx[FPS_T / 32], s_rcy[FPS_T / 32], s_rcz[FPS_T / 32];

    const int t  = threadIdx.x;
    const int cr = blockIdx.x;   // grid == cluster, so block idx == cluster rank
    const uint32_t slot_base = smem_u32(&s_slot[0][0][0]);
    const uint32_t mbar_base = smem_u32(&s_mbar[0]);

    if (t == 0) {
        asm volatile("mbarrier.init.shared.b64 [%0], 1;" :: "r"(mbar_base) : "memory");
        asm volatile("mbarrier.init.shared.b64 [%0], 1;" :: "r"(mbar_base + 8) : "memory");
    }
    // make mbarrier init visible cluster-wide before any st.async targets it
    asm volatile("barrier.cluster.arrive.aligned;" ::: "memory");
    asm volatile("barrier.cluster.wait.aligned;" ::: "memory");

    const int base = cr * PPC + t;
    float px[PPT], py[PPT], pz[PPT], pd[PPT];
#pragma unroll
    for (int k = 0; k < PPT; k++) {
        int p = base + k * FPS_T;
        px[k] = d_sx[p];
        py[k] = d_sy[p];
        pz[k] = d_sz[p];
        pd[k] = 1e38f;
    }

    // starting centroid = point 0 (broadcast load, same address all lanes)
    float cx = d_sx[0], cy = d_sy[0], cz = d_sz[0];

    int ph0 = 0, ph1 = 0;

    for (int i = 0; i < M_CENT; i++) {
        if (cr == 0 && t == 0) {
            new_xyz[3 * i + 0] = cx;
            new_xyz[3 * i + 1] = cy;
            new_xyz[3 * i + 2] = cz;
        }
        if (i == M_CENT - 1) break;

        // ---- distance update + per-thread argmax (carrying coords) ----
        float bd = -1.0f, bcx = 0.f, bcy = 0.f, bcz = 0.f;
        unsigned bi = 0;
#pragma unroll
        for (int k = 0; k < PPT; k++) {
            float dx = px[k] - cx;
            float dy = py[k] - cy;
            float dz = pz[k] - cz;
            // match XLA rounding: (dx*dx + dy*dy) + dz*dz, no FMA contraction
            float d = __fadd_rn(__fadd_rn(__fmul_rn(dx, dx), __fmul_rn(dy, dy)),
                                __fmul_rn(dz, dz));
            float nd = fminf(pd[k], d);
            pd[k] = nd;
            bool p = nd > bd;   // strict > : lowest index wins within thread
            bd  = p ? nd    : bd;
            bi  = p ? (unsigned)(base + k * FPS_T) : bi;
            bcx = p ? px[k] : bcx;
            bcy = p ? py[k] : bcy;
            bcz = p ? pz[k] : bcz;
        }

        // packed key: larger dist wins; equal dist -> smaller index wins
        unsigned long long key =
            ((unsigned long long)__float_as_uint(bd) << 32) |
            (unsigned long long)(0xFFFFFFFFu - bi);

        // ---- warp reduce (key + coords) ----
#pragma unroll
        for (int o = 16; o > 0; o >>= 1) {
            unsigned long long ok = __shfl_xor_sync(0xFFFFFFFFu, key, o);
            float ox = __shfl_xor_sync(0xFFFFFFFFu, bcx, o);
            float oy = __shfl_xor_sync(0xFFFFFFFFu, bcy, o);
            float oz = __shfl_xor_sync(0xFFFFFFFFu, bcz, o);
            if (ok > key) { key = ok; bcx = ox; bcy = oy; bcz = oz; }
        }
        if ((t & 31) == 0) {
            int w = t >> 5;
            s_rkey[w] = key; s_rcx[w] = bcx; s_rcy[w] = bcy; s_rcz[w] = bcz;
        }
        __syncthreads();   // also orders: all slot reads done before t0 sends

        const int nb = (i + 1) & 1;
        const uint32_t mb = mbar_base + nb * 8;

        // ---- CTA-level reduce (warp 0) + broadcast send (t0) ----
        if (t < 32) {
            int w = t & 15;   // lanes 16..31 duplicate 0..15 (harmless for max)
            key = s_rkey[w]; bcx = s_rcx[w]; bcy = s_rcy[w]; bcz = s_rcz[w];
#pragma unroll
            for (int o = 8; o > 0; o >>= 1) {
                unsigned long long ok = __shfl_xor_sync(0xFFFFFFFFu, key, o);
                float ox = __shfl_xor_sync(0xFFFFFFFFu, bcx, o);
                float oy = __shfl_xor_sync(0xFFFFFFFFu, bcy, o);
                float oz = __shfl_xor_sync(0xFFFFFFFFu, bcz, o);
                if (ok > key) { key = ok; bcx = ox; bcy = oy; bcz = oz; }
            }
            if (t == 0) {
                // post expected bytes for the upcoming phase (tx may go negative
                // if peers land first -- allowed, tx-count is signed)
                asm volatile("mbarrier.arrive.expect_tx.shared.b64 _, [%0], %1;"
                             :: "r"(mb), "r"((uint32_t)EXPECT_TX) : "memory");
                unsigned long long cxy =
                    ((unsigned long long)__float_as_uint(bcy) << 32) |
                    (unsigned long long)__float_as_uint(bcx);
                unsigned long long czz = (unsigned long long)__float_as_uint(bcz);
                const uint32_t ls = slot_base + (nb * FPS_CTAS + cr) * SLOT_BYTES;
#pragma unroll
                for (int r = 0; r < FPS_CTAS; r++) {
                    uint32_t rs, rm;
                    asm("mapa.shared::cluster.u32 %0, %1, %2;" : "=r"(rs) : "r"(ls), "r"(r));
                    asm("mapa.shared::cluster.u32 %0, %1, %2;" : "=r"(rm) : "r"(mb), "r"(r));
                    asm volatile("st.async.shared::cluster.mbarrier::complete_tx::bytes.b64 [%0], %1, [%2];"
                                 :: "r"(rs), "l"(key), "r"(rm) : "memory");
                    asm volatile("st.async.shared::cluster.mbarrier::complete_tx::bytes.b64 [%0], %1, [%2];"
                                 :: "r"(rs + 8), "l"(cxy), "r"(rm) : "memory");
                    asm volatile("st.async.shared::cluster.mbarrier::complete_tx::bytes.b64 [%0], %1, [%2];"
                                 :: "r"(rs + 16), "l"(czz), "r"(rm) : "memory");
                }
            }
        }

        // ---- wait for all 8 candidates, pick global winner locally ----
        int par = nb ? ph1 : ph0;
        mbar_wait(mb, (uint32_t)par);
        if (nb) ph1 ^= 1; else ph0 ^= 1;

        unsigned long long wk = 0ull; int wr = 0;
#pragma unroll
        for (int r = 0; r < FPS_CTAS; r++) {
            unsigned long long v = s_slot[nb][r][0];
            if (v > wk) { wk = v; wr = r; }
        }
        unsigned long long cxy = s_slot[nb][wr][1];
        unsigned long long czz = s_slot[nb][wr][2];
        cx = __uint_as_float((unsigned)(cxy & 0xFFFFFFFFull));
        cy = __uint_as_float((unsigned)(cxy >> 32));
        cz = __uint_as_float((unsigned)(czz & 0xFFFFFFFFull));
    }
}

// ---------------- kernel 2: ball query (top-32 smallest within radius) ----------------
#define BQ_T 256
#define CAP  4096

__global__ void __launch_bounds__(BQ_T)
bq_kernel(const float* __restrict__ new_xyz) {
    __shared__ unsigned long long list[CAP];
    __shared__ int s_cnt;
    __shared__ unsigned long long s_k[BQ_T / 32];
    __shared__ int s_p[BQ_T / 32];

    const int m = blockIdx.x, t = threadIdx.x;
    if (t == 0) s_cnt = 0;
    __syncthreads();

    const float cx = new_xyz[3 * m + 0];
    const float cy = new_xyz[3 * m + 1];
    const float cz = new_xyz[3 * m + 2];

    for (int p = t; p < N_PTS; p += BQ_T) {
        float dx = d_sx[p] - cx;
        float dy = d_sy[p] - cy;
        float dz = d_sz[p] - cz;
        float d2 = __fadd_rn(__fadd_rn(__fmul_rn(dx, dx), __fmul_rn(dy, dy)),
                             __fmul_rn(dz, dz));
        if (d2 <= RAD2) {
            int pos = atomicAdd(&s_cnt, 1);
            if (pos < CAP)
                list[pos] = ((unsigned long long)__float_as_uint(d2) << 32) |
                            (unsigned long long)(unsigned)p;
        }
    }
    __syncthreads();

    int n = s_cnt;
    if (n > CAP) n = CAP;

    if (n > K_NB) {
        for (int r = 0; r < K_NB; r++) {
            unsigned long long k = ~0ull; int pos = -1;
            for (int q = t; q < n; q += BQ_T) {
                unsigned long long v = list[q];
                if (v < k) { k = v; pos = q; }
            }
#pragma unroll
            for (int o = 16; o > 0; o >>= 1) {
                unsigned long long k2 = __shfl_xor_sync(0xFFFFFFFFu, k, o);
                int p2 = __shfl_xor_sync(0xFFFFFFFFu, pos, o);
                if (k2 < k) { k = k2; pos = p2; }
            }
            if ((t & 31) == 0) { s_k[t >> 5] = k; s_p[t >> 5] = pos; }
            __syncthreads();
            if (t == 0) {
                unsigned long long bk = ~0ull; int bp = -1;
#pragma unroll
                for (int w = 0; w < BQ_T / 32; w++)
                    if (s_k[w] < bk) { bk = s_k[w]; bp = s_p[w]; }
                d_gidx[m * K_NB + r] = (int)(bk & 0xFFFFFFFFull);
                list[bp] = ~0ull;   // remove winner
            }
            __syncthreads();
        }
    } else {
        if (t == 0) {
            int w = 0;
            for (int q = 0; q < n; q++)
                d_gidx[m * K_NB + w++] = (int)(list[q] & 0xFFFFFFFFull);
            for (int p = 0; w < K_NB; p++) {
                float dx = d_sx[p] - cx;
                float dy = d_sy[p] - cy;
                float dz = d_sz[p] - cz;
                float d2 = __fadd_rn(__fadd_rn(__fmul_rn(dx, dx), __fmul_rn(dy, dy)),
                                     __fmul_rn(dz, dz));
                if (d2 > RAD2) d_gidx[m * K_NB + w++] = p;
            }
        }
    }
}

// ---------------- kernel 3: grouped MLP (67->64 GELU, 64->128 GELU) + max-pool ----------------
__device__ __forceinline__ float gelu_exact(float x) {
    return 0.5f * x * (1.0f + erff(x * 0.70710678118654752f));
}

#define MLP_T 128

__global__ void __launch_bounds__(MLP_T)
mlp_kernel(const float* __restrict__ xyz,  const float* __restrict__ feat,
           const float* __restrict__ W1,   const float* __restrict__ b1,
           const float* __restrict__ W2,   const float* __restrict__ b2,
           const float* __restrict__ new_xyz, float* __restrict__ pooled) {
    __shared__ float s_g[K_NB * D0];     // grouped input  [32][67]
    __shared__ float s_h[K_NB * H1DIM];  // hidden         [32][64]
    __shared__ int   s_idx[K_NB];

    const int m = blockIdx.x, t = threadIdx.x;
    if (t < K_NB) s_idx[t] = d_gidx[m * K_NB + t];
    __syncthreads();

    const float nx = new_xyz[3 * m + 0];
    const float ny = new_xyz[3 * m + 1];
    const float nz = new_xyz[3 * m + 2];

    // gather [g_xyz | feat]
    for (int e = t; e < K_NB * D0; e += MLP_T) {
        int j = e / D0, k = e - j * D0;
        int id = s_idx[j];
        float v;
        if (k < 3) {
            float c = (k == 0) ? nx : (k == 1) ? ny : nz;
            v = xyz[id * 3 + k] - c;
        } else {
            v = feat[id * D_IN + (k - 3)];
        }
        s_g[j * D0 + k] = v;
    }
    __syncthreads();

    // layer 1: thread t handles row j = t&31, channels [grp*16, grp*16+16)
    {
        const int j = t & 31, grp = t >> 5;
        float acc[16];
#pragma unroll
        for (int cc = 0; cc < 16; cc++) acc[cc] = __ldg(&b1[grp * 16 + cc]);
        for (int k = 0; k < D0; k++) {
            float gk = s_g[j * D0 + k];
            const float* w = &W1[k * H1DIM + grp * 16];
#pragma unroll
            for (int cc = 0; cc < 16; cc++)
                acc[cc] = fmaf(gk, __ldg(&w[cc]), acc[cc]);
        }
#pragma unroll
        for (int cc = 0; cc < 16; cc++)
            s_h[j * H1DIM + grp * 16 + cc] = gelu_exact(acc[cc]);
    }
    __syncthreads();

    // layer 2 + max-pool: thread t == output channel; 4-row register tile over j
    {
        float pm = -3.4e38f;
        const float bb = __ldg(&b2[t]);
        for (int j0 = 0; j0 < K_NB; j0 += 4) {
            float a0 = bb, a1 = bb, a2 = bb, a3 = bb;
            const float* h0 = &s_h[(j0 + 0) * H1DIM];
            const float* h1 = &s_h[(j0 + 1) * H1DIM];
            const float* h2 = &s_h[(j0 + 2) * H1DIM];
            const float* h3 = &s_h[(j0 + 3) * H1DIM];
            for (int k = 0; k < H1DIM; k++) {
                float w = __ldg(&W2[k * H2DIM + t]);
                a0 = fmaf(h0[k], w, a0);
                a1 = fmaf(h1[k], w, a1);
                a2 = fmaf(h2[k], w, a2);
                a3 = fmaf(h3[k], w, a3);
            }
            pm = fmaxf(pm, gelu_exact(a0));
            pm = fmaxf(pm, gelu_exact(a1));
            pm = fmaxf(pm, gelu_exact(a2));
            pm = fmaxf(pm, gelu_exact(a3));
        }
        pooled[m * H2DIM + t] = pm;
    }
}

// ---------------- launch ----------------
extern "C" void kernel_launch(void* const* d_in, const int* in_sizes, int n_in,
                              void* d_out, int out_size) {
    const float* xyz  = (const float*)d_in[0];
    const float* feat = (const float*)d_in[1];
    const float* W1   = (const float*)d_in[2];
    const float* b1   = (const float*)d_in[3];
    const float* W2   = (const float*)d_in[4];
    const float* b2   = (const float*)d_in[5];

    float* out     = (float*)d_out;
    float* new_xyz = out;                 // [2048, 3]
    float* pooled  = out + M_CENT * 3;    // [2048, 128]

    transpose_kernel<<<(N_PTS + 255) / 256, 256>>>(xyz);
    fps_kernel<<<FPS_CTAS, FPS_T>>>(new_xyz);
    bq_kernel<<<M_CENT, BQ_T>>>(new_xyz);
    mlp_kernel<<<M_CENT, MLP_T>>>(xyz, feat, W1, b1, W2, b2, new_xyz, pooled);
}

// round 3
// speedup vs baseline: 3.0551x; 1.3089x over previous
#include <cuda_runtime.h>
#include <math.h>
#include <stdint.h>

#define N_PTS   32768
#define M_CENT  2048
#define K_NB    32
#define D_IN    64
#define D0      67
#define H1DIM   64
#define H2DIM   128
#define RAD2    0.25f

typedef unsigned long long ull;

// ---------------- device scratch (no allocation allowed) ----------------
__device__ float d_sx[N_PTS];
__device__ float d_sy[N_PTS];
__device__ float d_sz[N_PTS];
__device__ int   d_gidx[M_CENT * K_NB];

__device__ __forceinline__ uint32_t smem_u32(const void* p) {
    uint32_t a;
    asm("{ .reg .u64 t; cvta.to.shared.u64 t, %1; cvt.u32.u64 %0, t; }"
        : "=r"(a) : "l"(p));
    return a;
}
__device__ __forceinline__ ull pk2(float lo, float hi) {
    ull r; asm("mov.b64 %0, {%1, %2};" : "=l"(r) : "f"(lo), "f"(hi)); return r;
}
__device__ __forceinline__ void up2(ull v, float& lo, float& hi) {
    asm("mov.b64 {%0, %1}, %2;" : "=f"(lo), "=f"(hi) : "l"(v));
}
#define ADDX2(o, a, b) asm("add.rn.f32x2 %0, %1, %2;" : "=l"(o) : "l"(a), "l"(b))
#define MULX2(o, a, b) asm("mul.rn.f32x2 %0, %1, %2;" : "=l"(o) : "l"(a), "l"(b))

// ---------------- kernel 0: AoS -> SoA transpose ----------------
__global__ void transpose_kernel(const float* __restrict__ xyz) {
    int i = blockIdx.x * blockDim.x + threadIdx.x;
    if (i < N_PTS) {
        d_sx[i] = xyz[3 * i + 0];
        d_sy[i] = xyz[3 * i + 1];
        d_sz[i] = xyz[3 * i + 2];
    }
}

// ---------------- kernel 1: farthest point sampling ----------------
#define FPS_CTAS 8
#define FPS_T    512
#define NW       (FPS_T / 32)         // 16 warps
#define PPC      (N_PTS / FPS_CTAS)   // 4096
#define PPT      (PPC / FPS_T)        // 8
#define PRS      (PPT / 2)            // 4 packed pairs
#define SLOT_BYTES 24
#define EXPECT_TX  (FPS_CTAS * SLOT_BYTES)  // 192

__device__ __forceinline__ void mbar_wait(uint32_t mbar, uint32_t parity) {
    asm volatile(
        "{\n\t"
        ".reg .pred P;\n\t"
        "WAIT_%=:\n\t"
        "mbarrier.try_wait.parity.acquire.cta.shared::cta.b64 P, [%0], %1, 0x989680;\n\t"
        "@P bra DONE_%=;\n\t"
        "bra WAIT_%=;\n\t"
        "DONE_%=:\n\t"
        "}"
        :: "r"(mbar), "r"(parity) : "memory");
}

__global__ void __cluster_dims__(FPS_CTAS, 1, 1) __launch_bounds__(FPS_T, 1)
fps_kernel(float* __restrict__ new_xyz) {
    __shared__ ull      s_slot[2][FPS_CTAS][3];  // [buf][rank][key,cxy,cz]
    __shared__ ull      s_mbar[2];
    __shared__ unsigned s_pd[NW];     // per-warp winner dist bits
    __shared__ unsigned s_pi[NW];     // per-warp winner index
    __shared__ ull      s_pxy[NW];    // per-warp winner (x,y)
    __shared__ float    s_pz[NW];     // per-warp winner z

    const int t    = threadIdx.x;
    const int lane = t & 31;
    const int w    = t >> 5;
    const int cr   = blockIdx.x;  // grid == cluster
    const uint32_t slot_base = smem_u32(&s_slot[0][0][0]);
    const uint32_t mbar_base = smem_u32(&s_mbar[0]);

    if (t == 0) {
        asm volatile("mbarrier.init.shared.b64 [%0], 1;" :: "r"(mbar_base) : "memory");
        asm volatile("mbarrier.init.shared.b64 [%0], 1;" :: "r"(mbar_base + 8) : "memory");
    }
    asm volatile("barrier.cluster.arrive.aligned;" ::: "memory");
    asm volatile("barrier.cluster.wait.aligned;" ::: "memory");

    const int base = cr * PPC + t;
    ull pxp[PRS], pyp[PRS], pzp[PRS];
    float pd[PPT];
#pragma unroll
    for (int j = 0; j < PRS; j++) {
        int p0 = base + (2 * j) * FPS_T;
        int p1 = base + (2 * j + 1) * FPS_T;
        pxp[j] = pk2(d_sx[p0], d_sx[p1]);
        pyp[j] = pk2(d_sy[p0], d_sy[p1]);
        pzp[j] = pk2(d_sz[p0], d_sz[p1]);
        pd[2 * j] = 1e38f; pd[2 * j + 1] = 1e38f;
    }

    float cx = d_sx[0], cy = d_sy[0], cz = d_sz[0];
    int ph0 = 0, ph1 = 0;

    for (int i = 0; i < M_CENT; i++) {
        if (cr == 0 && t == 0) {
            new_xyz[3 * i + 0] = cx;
            new_xyz[3 * i + 1] = cy;
            new_xyz[3 * i + 2] = cz;
        }
        if (i == M_CENT - 1) break;

        // ---- packed distance update + scalar argmax tracking ----
        const ull ncx = pk2(-cx, -cx), ncy = pk2(-cy, -cy), ncz = pk2(-cz, -cz);
        float bd = -1.0f, bcx = 0.f, bcy = 0.f, bcz = 0.f;
        unsigned bi = 0;
#pragma unroll
        for (int j = 0; j < PRS; j++) {
            ull dx, dy, dz, xx, yy, zz, s;
            ADDX2(dx, pxp[j], ncx);          // p - c  (== p + (-c), exact)
            ADDX2(dy, pyp[j], ncy);
            ADDX2(dz, pzp[j], ncz);
            MULX2(xx, dx, dx);
            MULX2(yy, dy, dy);
            MULX2(zz, dz, dz);
            ADDX2(s, xx, yy);                // (dx^2 + dy^2)
            ADDX2(s, s, zz);                 // + dz^2   (XLA rounding order)
            float s0, s1; up2(s, s0, s1);
            float nd0 = fminf(pd[2 * j], s0);     pd[2 * j] = nd0;
            float nd1 = fminf(pd[2 * j + 1], s1); pd[2 * j + 1] = nd1;
            float x0, x1, y0, y1, z0, z1;
            up2(pxp[j], x0, x1); up2(pyp[j], y0, y1); up2(pzp[j], z0, z1);
            if (nd0 > bd) { bd = nd0; bi = (unsigned)(base + (2 * j) * FPS_T);
                            bcx = x0; bcy = y0; bcz = z0; }
            if (nd1 > bd) { bd = nd1; bi = (unsigned)(base + (2 * j + 1) * FPS_T);
                            bcx = x1; bcy = y1; bcz = z1; }
        }

        // ---- warp argmax via redux (dist bits are non-negative floats) ----
        {
            unsigned db  = __float_as_uint(bd);
            unsigned rb  = __reduce_max_sync(0xFFFFFFFFu, db);
            unsigned cnd = (db == rb) ? bi : 0xFFFFFFFFu;
            unsigned rbi = __reduce_min_sync(0xFFFFFFFFu, cnd);
            unsigned wl  = __ffs(__ballot_sync(0xFFFFFFFFu, cnd == rbi)) - 1;
            float wx = __shfl_sync(0xFFFFFFFFu, bcx, wl);
            float wy = __shfl_sync(0xFFFFFFFFu, bcy, wl);
            float wz = __shfl_sync(0xFFFFFFFFu, bcz, wl);
            if (lane == 0) {
                s_pd[w] = rb; s_pi[w] = rbi; s_pxy[w] = pk2(wx, wy); s_pz[w] = wz;
            }
        }
        __syncthreads();   // also orders prior slot reads before new sends

        const int nb = (i + 1) & 1;
        const uint32_t mb = mbar_base + nb * 8;

        // ---- CTA argmax (warp 0) + parallel DSMEM fan-out (lanes 0..7) ----
        if (w == 0) {
            unsigned db  = (lane < NW) ? s_pd[lane] : 0u;
            unsigned pbi = (lane < NW) ? s_pi[lane] : 0xFFFFFFFFu;
            ull      pxy = (lane < NW) ? s_pxy[lane] : 0ull;
            float    pz  = (lane < NW) ? s_pz[lane] : 0.f;
            unsigned rb  = __reduce_max_sync(0xFFFFFFFFu, db);
            unsigned cnd = (db == rb) ? pbi : 0xFFFFFFFFu;
            unsigned rbi = __reduce_min_sync(0xFFFFFFFFu, cnd);
            unsigned wl  = __ffs(__ballot_sync(0xFFFFFFFFu, cnd == rbi)) - 1;
            ull   cxy = __shfl_sync(0xFFFFFFFFu, pxy, wl);
            float czf = __shfl_sync(0xFFFFFFFFu, pz, wl);

            if (lane == 0) {
                asm volatile("mbarrier.arrive.expect_tx.shared.b64 _, [%0], %1;"
                             :: "r"(mb), "r"((uint32_t)EXPECT_TX) : "memory");
            }
            if (lane < FPS_CTAS) {
                ull key = ((ull)rb << 32) | (ull)(0xFFFFFFFFu - rbi);
                ull czz = (ull)__float_as_uint(czf);
                const uint32_t ls = slot_base + (nb * FPS_CTAS + cr) * SLOT_BYTES;
                uint32_t rs, rm;
                asm("mapa.shared::cluster.u32 %0, %1, %2;" : "=r"(rs) : "r"(ls), "r"(lane));
                asm("mapa.shared::cluster.u32 %0, %1, %2;" : "=r"(rm) : "r"(mb), "r"(lane));
                asm volatile("st.async.shared::cluster.mbarrier::complete_tx::bytes.b64 [%0], %1, [%2];"
                             :: "r"(rs), "l"(key), "r"(rm) : "memory");
                asm volatile("st.async.shared::cluster.mbarrier::complete_tx::bytes.b64 [%0], %1, [%2];"
                             :: "r"(rs + 8), "l"(cxy), "r"(rm) : "memory");
                asm volatile("st.async.shared::cluster.mbarrier::complete_tx::bytes.b64 [%0], %1, [%2];"
                             :: "r"(rs + 16), "l"(czz), "r"(rm) : "memory");
            }
        }

        // ---- wait for all 8 candidates, pick global winner locally ----
        int par = nb ? ph1 : ph0;
        mbar_wait(mb, (uint32_t)par);
        if (nb) ph1 ^= 1; else ph0 ^= 1;

        ull wk = 0ull; int wr = 0;
#pragma unroll
        for (int r = 0; r < FPS_CTAS; r++) {
            ull v = s_slot[nb][r][0];
            if (v > wk) { wk = v; wr = r; }
        }
        ull cxy = s_slot[nb][wr][1];
        ull czz = s_slot[nb][wr][2];
        up2(cxy, cx, cy);
        cz = __uint_as_float((unsigned)(czz & 0xFFFFFFFFull));
    }
}

// ---------------- kernel 2: ball query (top-32 smallest within radius) ----------------
#define BQ_T 256
#define CAP  4096

__global__ void __launch_bounds__(BQ_T)
bq_kernel(const float* __restrict__ new_xyz) {
    __shared__ ull list[CAP];
    __shared__ int s_cnt;
    __shared__ ull s_k[BQ_T / 32];
    __shared__ int s_p[BQ_T / 32];

    const int m = blockIdx.x, t = threadIdx.x;
    if (t == 0) s_cnt = 0;
    __syncthreads();

    const float cx = new_xyz[3 * m + 0];
    const float cy = new_xyz[3 * m + 1];
    const float cz = new_xyz[3 * m + 2];

    for (int p = t; p < N_PTS; p += BQ_T) {
        float dx = d_sx[p] - cx;
        float dy = d_sy[p] - cy;
        float dz = d_sz[p] - cz;
        float d2 = __fadd_rn(__fadd_rn(__fmul_rn(dx, dx), __fmul_rn(dy, dy)),
                             __fmul_rn(dz, dz));
        if (d2 <= RAD2) {
            int pos = atomicAdd(&s_cnt, 1);
            if (pos < CAP)
                list[pos] = ((ull)__float_as_uint(d2) << 32) | (ull)(unsigned)p;
        }
    }
    __syncthreads();

    int n = s_cnt;
    if (n > CAP) n = CAP;

    if (n > K_NB) {
        for (int r = 0; r < K_NB; r++) {
            ull k = ~0ull; int pos = -1;
            for (int q = t; q < n; q += BQ_T) {
                ull v = list[q];
                if (v < k) { k = v; pos = q; }
            }
#pragma unroll
            for (int o = 16; o > 0; o >>= 1) {
                ull k2 = __shfl_xor_sync(0xFFFFFFFFu, k, o);
                int p2 = __shfl_xor_sync(0xFFFFFFFFu, pos, o);
                if (k2 < k) { k = k2; pos = p2; }
            }
            if ((t & 31) == 0) { s_k[t >> 5] = k; s_p[t >> 5] = pos; }
            __syncthreads();
            if (t == 0) {
                ull bk = ~0ull; int bp = -1;
#pragma unroll
                for (int w = 0; w < BQ_T / 32; w++)
                    if (s_k[w] < bk) { bk = s_k[w]; bp = s_p[w]; }
                d_gidx[m * K_NB + r] = (int)(bk & 0xFFFFFFFFull);
                list[bp] = ~0ull;
            }
            __syncthreads();
        }
    } else {
        if (t == 0) {
            int w = 0;
            for (int q = 0; q < n; q++)
                d_gidx[m * K_NB + w++] = (int)(list[q] & 0xFFFFFFFFull);
            for (int p = 0; w < K_NB; p++) {
                float dx = d_sx[p] - cx;
                float dy = d_sy[p] - cy;
                float dz = d_sz[p] - cz;
                float d2 = __fadd_rn(__fadd_rn(__fmul_rn(dx, dx), __fmul_rn(dy, dy)),
                                     __fmul_rn(dz, dz));
                if (d2 > RAD2) d_gidx[m * K_NB + w++] = p;
            }
        }
    }
}

// ---------------- kernel 3: grouped MLP + max-pool ----------------
__device__ __forceinline__ float gelu_exact(float x) {
    return 0.5f * x * (1.0f + erff(x * 0.70710678118654752f));
}

#define MLP_T 128

__global__ void __launch_bounds__(MLP_T)
mlp_kernel(const float* __restrict__ xyz,  const float* __restrict__ feat,
           const float* __restrict__ W1,   const float* __restrict__ b1,
           const float* __restrict__ W2,   const float* __restrict__ b2,
           const float* __restrict__ new_xyz, float* __restrict__ pooled) {
    __shared__ __align__(16) float s_g[K_NB * D0];     // [32][67]
    __shared__ __align__(16) float s_h[K_NB * H1DIM];  // [32][64]
    __shared__ int s_idx[K_NB];

    const int m = blockIdx.x, t = threadIdx.x;
    if (t < K_NB) s_idx[t] = d_gidx[m * K_NB + t];
    __syncthreads();

    const float nx = new_xyz[3 * m + 0];
    const float ny = new_xyz[3 * m + 1];
    const float nz = new_xyz[3 * m + 2];

    for (int e = t; e < K_NB * D0; e += MLP_T) {
        int j = e / D0, k = e - j * D0;
        int id = s_idx[j];
        float v;
        if (k < 3) {
            float c = (k == 0) ? nx : (k == 1) ? ny : nz;
            v = xyz[id * 3 + k] - c;
        } else {
            v = feat[id * D_IN + (k - 3)];
        }
        s_g[j * D0 + k] = v;
    }
    __syncthreads();

    // layer 1: row j = t&31, 16 channels per thread, vectorized W1 loads
    {
        const int j = t & 31, grp = t >> 5;
        float acc[16];
        const float4* bv = reinterpret_cast<const float4*>(&b1[grp * 16]);
#pragma unroll
        for (int q = 0; q < 4; q++) {
            float4 b4 = __ldg(&bv[q]);
            acc[q * 4 + 0] = b4.x; acc[q * 4 + 1] = b4.y;
            acc[q * 4 + 2] = b4.z; acc[q * 4 + 3] = b4.w;
        }
        for (int k = 0; k < D0; k++) {
            float gk = s_g[j * D0 + k];
            const float4* wv = reinterpret_cast<const float4*>(&W1[k * H1DIM + grp * 16]);
#pragma unroll
            for (int q = 0; q < 4; q++) {
                float4 w4 = __ldg(&wv[q]);
                acc[q * 4 + 0] = fmaf(gk, w4.x, acc[q * 4 + 0]);
                acc[q * 4 + 1] = fmaf(gk, w4.y, acc[q * 4 + 1]);
                acc[q * 4 + 2] = fmaf(gk, w4.z, acc[q * 4 + 2]);
                acc[q * 4 + 3] = fmaf(gk, w4.w, acc[q * 4 + 3]);
            }
        }
#pragma unroll
        for (int cc = 0; cc < 16; cc++)
            s_h[j * H1DIM + grp * 16 + cc] = gelu_exact(acc[cc]);
    }
    __syncthreads();

    // layer 2 + max-pool: thread t == output channel, float4 LDS on s_h
    {
        float pm = -3.4e38f;
        const float bb = __ldg(&b2[t]);
        for (int j0 = 0; j0 < K_NB; j0 += 4) {
            float a0 = bb, a1 = bb, a2 = bb, a3 = bb;
            const float4* h0 = reinterpret_cast<const float4*>(&s_h[(j0 + 0) * H1DIM]);
            const float4* h1 = reinterpret_cast<const float4*>(&s_h[(j0 + 1) * H1DIM]);
            const float4* h2 = reinterpret_cast<const float4*>(&s_h[(j0 + 2) * H1DIM]);
            const float4* h3 = reinterpret_cast<const float4*>(&s_h[(j0 + 3) * H1DIM]);
#pragma unroll 4
            for (int k4 = 0; k4 < H1DIM / 4; k4++) {
                float w0 = __ldg(&W2[(k4 * 4 + 0) * H2DIM + t]);
                float w1 = __ldg(&W2[(k4 * 4 + 1) * H2DIM + t]);
                float w2 = __ldg(&W2[(k4 * 4 + 2) * H2DIM + t]);
                float w3 = __ldg(&W2[(k4 * 4 + 3) * H2DIM + t]);
                float4 v0 = h0[k4], v1 = h1[k4], v2 = h2[k4], v3 = h3[k4];
                a0 = fmaf(v0.x, w0, a0); a0 = fmaf(v0.y, w1, a0);
                a0 = fmaf(v0.z, w2, a0); a0 = fmaf(v0.w, w3, a0);
                a1 = fmaf(v1.x, w0, a1); a1 = fmaf(v1.y, w1, a1);
                a1 = fmaf(v1.z, w2, a1); a1 = fmaf(v1.w, w3, a1);
                a2 = fmaf(v2.x, w0, a2); a2 = fmaf(v2.y, w1, a2);
                a2 = fmaf(v2.z, w2, a2); a2 = fmaf(v2.w, w3, a2);
                a3 = fmaf(v3.x, w0, a3); a3 = fmaf(v3.y, w1, a3);
                a3 = fmaf(v3.z, w2, a3); a3 = fmaf(v3.w, w3, a3);
            }
            pm = fmaxf(pm, gelu_exact(a0));
            pm = fmaxf(pm, gelu_exact(a1));
            pm = fmaxf(pm, gelu_exact(a2));
            pm = fmaxf(pm, gelu_exact(a3));
        }
        pooled[m * H2DIM + t] = pm;
    }
}

// ---------------- launch ----------------
extern "C" void kernel_launch(void* const* d_in, const int* in_sizes, int n_in,
                              void* d_out, int out_size) {
    const float* xyz  = (const float*)d_in[0];
    const float* feat = (const float*)d_in[1];
    const float* W1   = (const float*)d_in[2];
    const float* b1   = (const float*)d_in[3];
    const float* W2   = (const float*)d_in[4];
    const float* b2   = (const float*)d_in[5];

    float* out     = (float*)d_out;
    float* new_xyz = out;                 // [2048, 3]
    float* pooled  = out + M_CENT * 3;    // [2048, 128]

    transpose_kernel<<<(N_PTS + 255) / 256, 256>>>(xyz);
    fps_kernel<<<FPS_CTAS, FPS_T>>>(new_xyz);
    bq_kernel<<<M_CENT, BQ_T>>>(new_xyz);
    mlp_kernel<<<M_CENT, MLP_T>>>(xyz, feat, W1, b1, W2, b2, new_xyz, pooled);
}

// round 4
// speedup vs baseline: 3.6127x; 1.1825x over previous
#include <cuda_runtime.h>
#include <math.h>
#include <stdint.h>

#define N_PTS   32768
#define M_CENT  2048
#define K_NB    32
#define D_IN    64
#define D0      67
#define H1DIM   64
#define H2DIM   128
#define RAD2    0.25f

typedef unsigned long long ull;

// ---------------- device scratch (no allocation allowed) ----------------
__device__ float d_sx[N_PTS];
__device__ float d_sy[N_PTS];
__device__ float d_sz[N_PTS];
__device__ int   d_gidx[M_CENT * K_NB];

__device__ __forceinline__ uint32_t smem_u32(const void* p) {
    uint32_t a;
    asm("{ .reg .u64 t; cvta.to.shared.u64 t, %1; cvt.u32.u64 %0, t; }"
        : "=r"(a) : "l"(p));
    return a;
}
__device__ __forceinline__ ull pk2(float lo, float hi) {
    ull r; asm("mov.b64 %0, {%1, %2};" : "=l"(r) : "f"(lo), "f"(hi)); return r;
}
__device__ __forceinline__ void up2(ull v, float& lo, float& hi) {
    asm("mov.b64 {%0, %1}, %2;" : "=f"(lo), "=f"(hi) : "l"(v));
}
#define ADDX2(o, a, b) asm("add.rn.f32x2 %0, %1, %2;" : "=l"(o) : "l"(a), "l"(b))
#define MULX2(o, a, b) asm("mul.rn.f32x2 %0, %1, %2;" : "=l"(o) : "l"(a), "l"(b))

// ---------------- kernel 0: AoS -> SoA transpose ----------------
__global__ void transpose_kernel(const float* __restrict__ xyz) {
    int i = blockIdx.x * blockDim.x + threadIdx.x;
    if (i < N_PTS) {
        d_sx[i] = xyz[3 * i + 0];
        d_sy[i] = xyz[3 * i + 1];
        d_sz[i] = xyz[3 * i + 2];
    }
}

// ---------------- kernel 1: farthest point sampling ----------------
#define FPS_CTAS 8
#define FPS_T    512
#define NW       (FPS_T / 32)         // 16 warps
#define PPC      (N_PTS / FPS_CTAS)   // 4096
#define PPT      (PPC / FPS_T)        // 8
#define PRS      (PPT / 2)            // 4 packed pairs
#define SLOT_BYTES 24
#define EXPECT_TX  (FPS_CTAS * SLOT_BYTES)  // 192

// dynamic smem layout (bytes)
#define SM_X     0
#define SM_Y     (SM_X + PPC * 4)
#define SM_Z     (SM_Y + PPC * 4)
#define SM_SLOT  (SM_Z + PPC * 4)                     // [2][8][3] ull
#define SM_MBAR  (SM_SLOT + 2 * FPS_CTAS * 3 * 8)
#define SM_PD    (SM_MBAR + 16)
#define SM_PI    (SM_PD + NW * 4)
#define FPS_SMEM (SM_PI + NW * 4)

__device__ __forceinline__ void mbar_wait(uint32_t mbar, uint32_t parity) {
    asm volatile(
        "{\n\t"
        ".reg .pred P;\n\t"
        "WAIT_%=:\n\t"
        "mbarrier.try_wait.parity.acquire.cta.shared::cta.b64 P, [%0], %1, 0x989680;\n\t"
        "@P bra DONE_%=;\n\t"
        "bra WAIT_%=;\n\t"
        "DONE_%=:\n\t"
        "}"
        :: "r"(mbar), "r"(parity) : "memory");
}

__global__ void __cluster_dims__(FPS_CTAS, 1, 1) __launch_bounds__(FPS_T, 1)
fps_kernel(float* __restrict__ new_xyz) {
    extern __shared__ __align__(16) unsigned char smraw[];
    float*    s_x  = (float*)(smraw + SM_X);
    float*    s_y  = (float*)(smraw + SM_Y);
    float*    s_z  = (float*)(smraw + SM_Z);
    ull*      s_slot = (ull*)(smraw + SM_SLOT);   // [buf][rank][key,cxy,cz]
    unsigned* s_pd = (unsigned*)(smraw + SM_PD);
    unsigned* s_pi = (unsigned*)(smraw + SM_PI);

    const int t    = threadIdx.x;
    const int lane = t & 31;
    const int w    = t >> 5;
    const int cr   = blockIdx.x;  // grid == cluster
    const uint32_t slot_base = smem_u32(smraw + SM_SLOT);
    const uint32_t mbar_base = smem_u32(smraw + SM_MBAR);

    if (t == 0) {
        asm volatile("mbarrier.init.shared.b64 [%0], 1;" :: "r"(mbar_base) : "memory");
        asm volatile("mbarrier.init.shared.b64 [%0], 1;" :: "r"(mbar_base + 8) : "memory");
    }
    asm volatile("barrier.cluster.arrive.aligned;" ::: "memory");
    asm volatile("barrier.cluster.wait.aligned;" ::: "memory");

    const int base = cr * PPC + t;
    // SMEM mirror of this CTA's points (for winner coord lookup at send time)
    for (int p = t; p < PPC; p += FPS_T) {
        s_x[p] = d_sx[cr * PPC + p];
        s_y[p] = d_sy[cr * PPC + p];
        s_z[p] = d_sz[cr * PPC + p];
    }

    ull pxp[PRS], pyp[PRS], pzp[PRS];
    float pd[PPT];
#pragma unroll
    for (int j = 0; j < PRS; j++) {
        int p0 = base + (2 * j) * FPS_T;
        int p1 = base + (2 * j + 1) * FPS_T;
        pxp[j] = pk2(d_sx[p0], d_sx[p1]);
        pyp[j] = pk2(d_sy[p0], d_sy[p1]);
        pzp[j] = pk2(d_sz[p0], d_sz[p1]);
        pd[2 * j] = 1e38f; pd[2 * j + 1] = 1e38f;
    }

    float cx = d_sx[0], cy = d_sy[0], cz = d_sz[0];
    int ph0 = 0, ph1 = 0;

    for (int i = 0; i < M_CENT; i++) {
        if (cr == 0 && t == 0) {
            new_xyz[3 * i + 0] = cx;
            new_xyz[3 * i + 1] = cy;
            new_xyz[3 * i + 2] = cz;
        }
        if (i == M_CENT - 1) break;

        // ---- packed distance update, track (dist, idx) only ----
        const ull ncx = pk2(-cx, -cx), ncy = pk2(-cy, -cy), ncz = pk2(-cz, -cz);
        float bd = -1.0f;
        unsigned bi = 0;
#pragma unroll
        for (int j = 0; j < PRS; j++) {
            ull dx, dy, dz, xx, yy, zz, s;
            ADDX2(dx, pxp[j], ncx);          // p - c (== p + (-c), exact)
            ADDX2(dy, pyp[j], ncy);
            ADDX2(dz, pzp[j], ncz);
            MULX2(xx, dx, dx);
            MULX2(yy, dy, dy);
            MULX2(zz, dz, dz);
            ADDX2(s, xx, yy);                // (dx^2 + dy^2)
            ADDX2(s, s, zz);                 // + dz^2 (XLA rounding order)
            float s0, s1; up2(s, s0, s1);
            float nd0 = fminf(pd[2 * j], s0);     pd[2 * j] = nd0;
            float nd1 = fminf(pd[2 * j + 1], s1); pd[2 * j + 1] = nd1;
            if (nd0 > bd) { bd = nd0; bi = (unsigned)(base + (2 * j) * FPS_T); }
            if (nd1 > bd) { bd = nd1; bi = (unsigned)(base + (2 * j + 1) * FPS_T); }
        }

        // ---- warp argmax via redux (dist bits non-negative -> u32 monotonic) ----
        {
            unsigned db  = __float_as_uint(bd);
            unsigned rb  = __reduce_max_sync(0xFFFFFFFFu, db);
            unsigned cnd = (db == rb) ? bi : 0xFFFFFFFFu;
            unsigned rbi = __reduce_min_sync(0xFFFFFFFFu, cnd);
            if (lane == 0) { s_pd[w] = rb; s_pi[w] = rbi; }
        }
        __syncthreads();   // also orders prior slot reads before new sends

        const int nb = (i + 1) & 1;
        const uint32_t mb = mbar_base + nb * 8;

        // ---- CTA argmax (warp 0) + parallel DSMEM fan-out (lanes 0..7) ----
        if (w == 0) {
            unsigned db  = (lane < NW) ? s_pd[lane] : 0u;
            unsigned pbi = (lane < NW) ? s_pi[lane] : 0xFFFFFFFFu;
            unsigned rb  = __reduce_max_sync(0xFFFFFFFFu, db);
            unsigned cnd = (db == rb) ? pbi : 0xFFFFFFFFu;
            unsigned rbi = __reduce_min_sync(0xFFFFFFFFu, cnd);

            if (lane == 0) {
                asm volatile("mbarrier.arrive.expect_tx.shared.b64 _, [%0], %1;"
                             :: "r"(mb), "r"((uint32_t)EXPECT_TX) : "memory");
            }
            if (lane < FPS_CTAS) {
                int li = (int)rbi - cr * PPC;       // winner is always local
                float wx = s_x[li], wy = s_y[li], wz = s_z[li];  // broadcast LDS
                ull key = ((ull)rb << 32) | (ull)(0xFFFFFFFFu - rbi);
                ull cxy = pk2(wx, wy);
                ull czz = (ull)__float_as_uint(wz);
                const uint32_t ls = slot_base + (nb * FPS_CTAS + cr) * SLOT_BYTES;
                uint32_t rs, rm;
                asm("mapa.shared::cluster.u32 %0, %1, %2;" : "=r"(rs) : "r"(ls), "r"(lane));
                asm("mapa.shared::cluster.u32 %0, %1, %2;" : "=r"(rm) : "r"(mb), "r"(lane));
                asm volatile("st.async.shared::cluster.mbarrier::complete_tx::bytes.b64 [%0], %1, [%2];"
                             :: "r"(rs), "l"(key), "r"(rm) : "memory");
                asm volatile("st.async.shared::cluster.mbarrier::complete_tx::bytes.b64 [%0], %1, [%2];"
                             :: "r"(rs + 8), "l"(cxy), "r"(rm) : "memory");
                asm volatile("st.async.shared::cluster.mbarrier::complete_tx::bytes.b64 [%0], %1, [%2];"
                             :: "r"(rs + 16), "l"(czz), "r"(rm) : "memory");
            }
        }

        // ---- wait for all 8 candidates, pick global winner locally ----
        int par = nb ? ph1 : ph0;
        mbar_wait(mb, (uint32_t)par);
        if (nb) ph1 ^= 1; else ph0 ^= 1;

        ull wk = 0ull; int wr = 0;
#pragma unroll
        for (int r = 0; r < FPS_CTAS; r++) {
            ull v = s_slot[(nb * FPS_CTAS + r) * 3 + 0];
            if (v > wk) { wk = v; wr = r; }
        }
        ull cxy = s_slot[(nb * FPS_CTAS + wr) * 3 + 1];
        ull czz = s_slot[(nb * FPS_CTAS + wr) * 3 + 2];
        up2(cxy, cx, cy);
        cz = __uint_as_float((unsigned)(czz & 0xFFFFFFFFull));
    }
}

// ---------------- kernel 2: ball query (top-32 smallest within radius) ----------------
#define BQ_T 256
#define CAP  4096

__global__ void __launch_bounds__(BQ_T)
bq_kernel(const float* __restrict__ new_xyz) {
    __shared__ ull list[CAP];
    __shared__ int s_cnt;
    __shared__ ull s_k[BQ_T / 32];
    __shared__ int s_p[BQ_T / 32];

    const int m = blockIdx.x, t = threadIdx.x;
    if (t == 0) s_cnt = 0;
    __syncthreads();

    const float cx = new_xyz[3 * m + 0];
    const float cy = new_xyz[3 * m + 1];
    const float cz = new_xyz[3 * m + 2];

    for (int p = t; p < N_PTS; p += BQ_T) {
        float dx = d_sx[p] - cx;
        float dy = d_sy[p] - cy;
        float dz = d_sz[p] - cz;
        float d2 = __fadd_rn(__fadd_rn(__fmul_rn(dx, dx), __fmul_rn(dy, dy)),
                             __fmul_rn(dz, dz));
        if (d2 <= RAD2) {
            int pos = atomicAdd(&s_cnt, 1);
            if (pos < CAP)
                list[pos] = ((ull)__float_as_uint(d2) << 32) | (ull)(unsigned)p;
        }
    }
    __syncthreads();

    int n = s_cnt;
    if (n > CAP) n = CAP;

    if (n > K_NB) {
        for (int r = 0; r < K_NB; r++) {
            ull k = ~0ull; int pos = -1;
            for (int q = t; q < n; q += BQ_T) {
                ull v = list[q];
                if (v < k) { k = v; pos = q; }
            }
#pragma unroll
            for (int o = 16; o > 0; o >>= 1) {
                ull k2 = __shfl_xor_sync(0xFFFFFFFFu, k, o);
                int p2 = __shfl_xor_sync(0xFFFFFFFFu, pos, o);
                if (k2 < k) { k = k2; pos = p2; }
            }
            if ((t & 31) == 0) { s_k[t >> 5] = k; s_p[t >> 5] = pos; }
            __syncthreads();
            if (t == 0) {
                ull bk = ~0ull; int bp = -1;
#pragma unroll
                for (int w = 0; w < BQ_T / 32; w++)
                    if (s_k[w] < bk) { bk = s_k[w]; bp = s_p[w]; }
                d_gidx[m * K_NB + r] = (int)(bk & 0xFFFFFFFFull);
                list[bp] = ~0ull;
            }
            __syncthreads();
        }
    } else {
        if (t == 0) {
            int w = 0;
            for (int q = 0; q < n; q++)
                d_gidx[m * K_NB + w++] = (int)(list[q] & 0xFFFFFFFFull);
            for (int p = 0; w < K_NB; p++) {
                float dx = d_sx[p] - cx;
                float dy = d_sy[p] - cy;
                float dz = d_sz[p] - cz;
                float d2 = __fadd_rn(__fadd_rn(__fmul_rn(dx, dx), __fmul_rn(dy, dy)),
                                     __fmul_rn(dz, dz));
                if (d2 > RAD2) d_gidx[m * K_NB + w++] = p;
            }
        }
    }
}

// ---------------- kernel 3: grouped MLP + max-pool ----------------
__device__ __forceinline__ float gelu_exact(float x) {
    return 0.5f * x * (1.0f + erff(x * 0.70710678118654752f));
}

#define MLP_T 128

__global__ void __launch_bounds__(MLP_T)
mlp_kernel(const float* __restrict__ xyz,  const float* __restrict__ feat,
           const float* __restrict__ W1,   const float* __restrict__ b1,
           const float* __restrict__ W2,   const float* __restrict__ b2,
           const float* __restrict__ new_xyz, float* __restrict__ pooled) {
    __shared__ __align__(16) float s_g[K_NB * D0];     // [32][67]
    __shared__ __align__(16) float s_h[K_NB * H1DIM];  // [32][64]
    __shared__ int s_idx[K_NB];

    const int m = blockIdx.x, t = threadIdx.x;
    if (t < K_NB) s_idx[t] = d_gidx[m * K_NB + t];
    __syncthreads();

    const float nx = new_xyz[3 * m + 0];
    const float ny = new_xyz[3 * m + 1];
    const float nz = new_xyz[3 * m + 2];

    for (int e = t; e < K_NB * D0; e += MLP_T) {
        int j = e / D0, k = e - j * D0;
        int id = s_idx[j];
        float v;
        if (k < 3) {
            float c = (k == 0) ? nx : (k == 1) ? ny : nz;
            v = xyz[id * 3 + k] - c;
        } else {
            v = feat[id * D_IN + (k - 3)];
        }
        s_g[j * D0 + k] = v;
    }
    __syncthreads();

    // layer 1: row j = t&31, 16 channels per thread, vectorized W1 loads
    {
        const int j = t & 31, grp = t >> 5;
        float acc[16];
        const float4* bv = reinterpret_cast<const float4*>(&b1[grp * 16]);
#pragma unroll
        for (int q = 0; q < 4; q++) {
            float4 b4 = __ldg(&bv[q]);
            acc[q * 4 + 0] = b4.x; acc[q * 4 + 1] = b4.y;
            acc[q * 4 + 2] = b4.z; acc[q * 4 + 3] = b4.w;
        }
        for (int k = 0; k < D0; k++) {
            float gk = s_g[j * D0 + k];
            const float4* wv = reinterpret_cast<const float4*>(&W1[k * H1DIM + grp * 16]);
#pragma unroll
            for (int q = 0; q < 4; q++) {
                float4 w4 = __ldg(&wv[q]);
                acc[q * 4 + 0] = fmaf(gk, w4.x, acc[q * 4 + 0]);
                acc[q * 4 + 1] = fmaf(gk, w4.y, acc[q * 4 + 1]);
                acc[q * 4 + 2] = fmaf(gk, w4.z, acc[q * 4 + 2]);
                acc[q * 4 + 3] = fmaf(gk, w4.w, acc[q * 4 + 3]);
            }
        }
#pragma unroll
        for (int cc = 0; cc < 16; cc++)
            s_h[j * H1DIM + grp * 16 + cc] = gelu_exact(acc[cc]);
    }
    __syncthreads();

    // layer 2 + max-pool: thread t == output channel, 8-row register tile
    {
        float pm = -3.4e38f;
        const float bb = __ldg(&b2[t]);
        for (int j0 = 0; j0 < K_NB; j0 += 8) {
            float acc[8];
#pragma unroll
            for (int r = 0; r < 8; r++) acc[r] = bb;
            for (int k4 = 0; k4 < H1DIM / 4; k4++) {
                float w0 = __ldg(&W2[(k4 * 4 + 0) * H2DIM + t]);
                float w1 = __ldg(&W2[(k4 * 4 + 1) * H2DIM + t]);
                float w2 = __ldg(&W2[(k4 * 4 + 2) * H2DIM + t]);
                float w3 = __ldg(&W2[(k4 * 4 + 3) * H2DIM + t]);
#pragma unroll
                for (int r = 0; r < 8; r++) {
                    float4 v = *reinterpret_cast<const float4*>(
                        &s_h[(j0 + r) * H1DIM + k4 * 4]);
                    acc[r] = fmaf(v.x, w0, acc[r]);
                    acc[r] = fmaf(v.y, w1, acc[r]);
                    acc[r] = fmaf(v.z, w2, acc[r]);
                    acc[r] = fmaf(v.w, w3, acc[r]);
                }
            }
#pragma unroll
            for (int r = 0; r < 8; r++)
                pm = fmaxf(pm, gelu_exact(acc[r]));
        }
        pooled[m * H2DIM + t] = pm;
    }
}

// ---------------- launch ----------------
extern "C" void kernel_launch(void* const* d_in, const int* in_sizes, int n_in,
                              void* d_out, int out_size) {
    const float* xyz  = (const float*)d_in[0];
    const float* feat = (const float*)d_in[1];
    const float* W1   = (const float*)d_in[2];
    const float* b1   = (const float*)d_in[3];
    const float* W2   = (const float*)d_in[4];
    const float* b2   = (const float*)d_in[5];

    float* out     = (float*)d_out;
    float* new_xyz = out;                 // [2048, 3]
    float* pooled  = out + M_CENT * 3;    // [2048, 128]

    cudaFuncSetAttribute(fps_kernel, cudaFuncAttributeMaxDynamicSharedMemorySize,
                         FPS_SMEM);

    transpose_kernel<<<(N_PTS + 255) / 256, 256>>>(xyz);
    fps_kernel<<<FPS_CTAS, FPS_T, FPS_SMEM>>>(new_xyz);
    bq_kernel<<<M_CENT, BQ_T>>>(new_xyz);
    mlp_kernel<<<M_CENT, MLP_T>>>(xyz, feat, W1, b1, W2, b2, new_xyz, pooled);
}